// round 7
// baseline (speedup 1.0000x reference)
#include <cuda_runtime.h>

#define NV 23
#define NN 529          // 23*23
#define TV 12
#define ROWLEN 6348     // N*N*T floats per batch
#define NTHREADS 544    // 17 warps; threads 529..543 idle but sync
#define NBLOCKS 296     // 148 SMs * 2 blocks
#define CHUNK 4         // batches per barrier

__global__ __launch_bounds__(NTHREADS, 2)
void gat_kernel(const float* __restrict__ flow,
                const int*   __restrict__ adj,
                const float* __restrict__ W,
                float*       __restrict__ out,
                int B)
{
    __shared__ float dbuf[2][CHUNK][NN];  // staged slices d[m*23+i]
    __shared__ int   adj_s[NN];

    const int tid = threadIdx.x;
    const bool act = (tid < NN);
    int i_idx = 0, k_idx = 0;
    if (act) { i_idx = tid / NV; k_idx = tid - i_idx * NV; }

    const int step    = gridDim.x * CHUNK;
    const int myfirst = blockIdx.x * CHUNK;
    const float* gsrc = flow + tid * TV + (TV - 1);   // this thread's gather point

    float nv[CHUNK];

    // ---- adjacency (and kick off first prefetch immediately) ----
    if (act) {
        int a = adj[tid];
        if (i_idx == k_idx) a = 1;
        adj_s[tid] = a;

        #pragma unroll
        for (int c = 0; c < CHUNK; ++c) {
            const int b = myfirst + c;
            nv[c] = (b < B) ? __ldg(gsrc + (size_t)b * ROWLEN) : 0.0f;
        }
    }
    __syncthreads();   // adj_s visible (loads still in flight)

    // ---- per-thread attention row att[i_idx][k_idx][0..22] (overlaps loads) ----
    float att[NV];
    if (act) {
        const float* wr = W + tid * NV;
        float mn = 0.0f;                       // = min(min_m W, 0)
        #pragma unroll
        for (int m = 0; m < NV; ++m) {
            att[m] = wr[m];
            mn = fminf(mn, att[m]);
        }
        float s = 0.0f;
        #pragma unroll
        for (int m = 0; m < NV; ++m) {
            float a = (adj_s[k_idx * NV + m] != 0) ? (att[m] - mn) : 0.0f;
            att[m] = a;
            s += a;
        }
        float inv = 1.0f / s;
        #pragma unroll
        for (int m = 0; m < NV; ++m) att[m] *= inv;
    }

    // ---- prologue: land chunk 0, then issue prefetch for chunk 1 ----
    if (act) {
        #pragma unroll
        for (int c = 0; c < CHUNK; ++c)
            dbuf[0][c][tid] = nv[c];

        #pragma unroll
        for (int c = 0; c < CHUNK; ++c) {
            const int b = myfirst + step + c;
            nv[c] = (b < B) ? __ldg(gsrc + (size_t)b * ROWLEN) : 0.0f;
        }
    }
    __syncthreads();

    // ---- main loop: compute → land prev prefetch → issue 2-ahead → sync ----
    int p = 0;
    for (int base = myfirst; base < B; base += step) {
        // 1) compute chunk 'base' from staged buffer (no load dependence)
        if (act) {
            #pragma unroll
            for (int c = 0; c < CHUNK; ++c) {
                const int b = base + c;
                if (b < B) {
                    const float* d = dbuf[p][c];
                    float acc = 0.0f;
                    #pragma unroll
                    for (int m = 0; m < NV; ++m)
                        acc = fmaf(att[m], d[m * NV + i_idx], acc);
                    out[(size_t)b * NN + tid] = acc;   // coalesced
                }
            }

            // 2) land loads issued LAST iteration (≈1 full iteration old)
            #pragma unroll
            for (int c = 0; c < CHUNK; ++c)
                dbuf[p ^ 1][c][tid] = nv[c];

            // 3) issue prefetch two steps ahead
            #pragma unroll
            for (int c = 0; c < CHUNK; ++c) {
                const int b = base + 2 * step + c;
                nv[c] = (b < B) ? __ldg(gsrc + (size_t)b * ROWLEN) : 0.0f;
            }
        }
        __syncthreads();
        p ^= 1;
    }
}

extern "C" void kernel_launch(void* const* d_in, const int* in_sizes, int n_in,
                              void* d_out, int out_size) {
    const float* flow = (const float*)d_in[0];   // (B, N, N, T) fp32
    const int*   adj  = (const int*)  d_in[1];   // (N, N) int32
    const float* W    = (const float*)d_in[2];   // (N, N, N) fp32
    float*       out  = (float*)d_out;           // (B, N, N, 1) fp32

    const int B = in_sizes[0] / ROWLEN;
    gat_kernel<<<NBLOCKS, NTHREADS>>>(flow, adj, W, out, B);
}

// round 8
// speedup vs baseline: 1.0842x; 1.0842x over previous
#include <cuda_runtime.h>

#define NV 23
#define NN 529          // 23*23
#define TV 12
#define ROWLEN 6348     // N*N*T floats per batch
#define NTHREADS 544    // 17 warps; threads 529..543 idle but sync
#define NBLOCKS 296     // 148 SMs * 2 blocks
#define CHUNK 8         // batches per barrier

__global__ __launch_bounds__(NTHREADS, 2)
void gat_kernel(const float* __restrict__ flow,
                const int*   __restrict__ adj,
                const float* __restrict__ W,
                float*       __restrict__ out,
                int B)
{
    __shared__ float dbuf[2][CHUNK][NN];  // staged slices d[m*23+i]
    __shared__ int   adj_s[NN];

    const int tid = threadIdx.x;
    const bool act = (tid < NN);
    int i_idx = 0, k_idx = 0;
    if (act) { i_idx = tid / NV; k_idx = tid - i_idx * NV; }

    // ---- adjacency with forced self-loops ----
    if (act) {
        int a = adj[tid];
        if (i_idx == k_idx) a = 1;
        adj_s[tid] = a;
    }
    __syncthreads();

    // ---- per-thread attention row att[i_idx][k_idx][0..22] in registers ----
    float att[NV];
    if (act) {
        const float* wr = W + tid * NV;
        float mn = 0.0f;                       // = min(min_m W, 0)
        #pragma unroll
        for (int m = 0; m < NV; ++m) {
            att[m] = wr[m];
            mn = fminf(mn, att[m]);
        }
        float s = 0.0f;
        #pragma unroll
        for (int m = 0; m < NV; ++m) {
            float a = (adj_s[k_idx * NV + m] != 0) ? (att[m] - mn) : 0.0f;
            att[m] = a;
            s += a;
        }
        float inv = 1.0f / s;
        #pragma unroll
        for (int m = 0; m < NV; ++m) att[m] *= inv;
    }

    // ---- chunked grid-stride batch loop, double-buffered, 1 barrier / 8 batches ----
    const int step = gridDim.x * CHUNK;
    int base = blockIdx.x * CHUNK;
    const float* gsrc = flow + tid * TV + (TV - 1);   // this thread's gather point

    // prologue: stage chunk at 'base'
    if (act) {
        #pragma unroll
        for (int c = 0; c < CHUNK; ++c) {
            const int b = base + c;
            float v = (b < B) ? __ldg(gsrc + (size_t)b * ROWLEN) : 0.0f;
            dbuf[0][c][tid] = v;
        }
    }
    __syncthreads();

    int p = 0;
    for (; base < B; base += step) {
        const int nbase = base + step;

        // prefetch next chunk FIRST: 8 independent scattered loads per thread
        float nv[CHUNK];
        if (act) {
            #pragma unroll
            for (int c = 0; c < CHUNK; ++c) {
                const int b = nbase + c;
                nv[c] = (b < B) ? __ldg(gsrc + (size_t)b * ROWLEN) : 0.0f;
            }
        }

        // compute 8 outputs from staged buffers (overlaps with prefetch latency)
        if (act) {
            #pragma unroll
            for (int c = 0; c < CHUNK; ++c) {
                const int b = base + c;
                if (b < B) {
                    const float* d = dbuf[p][c];
                    float acc = 0.0f;
                    #pragma unroll
                    for (int m = 0; m < NV; ++m)
                        acc = fmaf(att[m], d[m * NV + i_idx], acc);
                    out[(size_t)b * NN + tid] = acc;   // coalesced
                }
            }
        }

        // stage prefetched chunk into the other buffer
        if (act) {
            #pragma unroll
            for (int c = 0; c < CHUNK; ++c)
                dbuf[p ^ 1][c][tid] = nv[c];
        }
        __syncthreads();
        p ^= 1;
    }
}

extern "C" void kernel_launch(void* const* d_in, const int* in_sizes, int n_in,
                              void* d_out, int out_size) {
    const float* flow = (const float*)d_in[0];   // (B, N, N, T) fp32
    const int*   adj  = (const int*)  d_in[1];   // (N, N) int32
    const float* W    = (const float*)d_in[2];   // (N, N, N) fp32
    float*       out  = (float*)d_out;           // (B, N, N, 1) fp32

    const int B = in_sizes[0] / ROWLEN;
    gat_kernel<<<NBLOCKS, NTHREADS>>>(flow, adj, W, out, B);
}